// round 1
// baseline (speedup 1.0000x reference)
#include <cuda_runtime.h>
#include <cuda_bf16.h>

// HashEncoder: B=2^21 points, D=3, L=16 levels, C=2, HASHMAP=2^19.
// Levels 0..2 dense (res 16,32,64), levels 3..15 hashed (524288 rows each).
// One thread per (point, level). Output [B, 32] f32; thread t writes float2 at
// out2[t] with t = point*16 + level -> fully coalesced streaming stores.
//
// Gather optimization: entries are float2 (8B). The two corners differing only
// in dim0 have indices (h, h^1) whenever ix is even (PRIMES[0]==1 for hashed;
// stride 1 for dense), so one aligned float4 load fetches both -> 4 loads
// instead of 8 for ~half the threads. This is the L1tex-wavefront bottleneck.

#define HASHMASK 524287u
#define PRIME1   2654435761u
#define PRIME2   805459861u

__global__ void __launch_bounds__(256, 8) hashenc_kernel(
    const float*  __restrict__ x,
    const float2* __restrict__ emb,
    float2*       __restrict__ out,
    unsigned nthreads)
{
    unsigned t = blockIdx.x * 256u + threadIdx.x;
    if (t >= nthreads) return;
    unsigned p   = t >> 4;
    unsigned lvl = t & 15u;

    float xx = __ldg(x + p * 3u + 0u);
    float xy = __ldg(x + p * 3u + 1u);
    float xz = __ldg(x + p * 3u + 2u);

    unsigned res  = 16u << lvl;
    float    resf = (float)(res - 1u);

    float px = xx * resf, py = xy * resf, pz = xz * resf;
    float fx = floorf(px), fy = floorf(py), fz = floorf(pz);
    float rx = px - fx, ry = py - fy, rz = pz - fz;
    unsigned ix = (unsigned)(int)fx;
    unsigned iy = (unsigned)(int)fy;
    unsigned iz = (unsigned)(int)fz;

    // Row offsets: dense levels {0, 4096, 36864}; hashed 299008 + (l-3)*524288.
    unsigned offset;
    if (lvl >= 3u)      offset = 299008u + (lvl - 3u) * 524288u;
    else if (lvl == 2u) offset = 36864u;
    else if (lvl == 1u) offset = 4096u;
    else                offset = 0u;

    const float2* tab = emb + offset;

    float ax = 0.f, ay = 0.f;
    float w0x = 1.f - rx;
    bool even = (ix & 1u) == 0u;

    if (lvl < 3u) {
        // ---- dense: idx = ix + iy*res + iz*res^2, corner pair = idx, idx+1
        unsigned res2 = res * res;
        #pragma unroll
        for (int b2 = 0; b2 < 2; ++b2) {
            float    wz   = b2 ? rz : (1.f - rz);
            unsigned zoff = (iz + (unsigned)b2) * res2;
            #pragma unroll
            for (int b1 = 0; b1 < 2; ++b1) {
                float    wyz  = (b1 ? ry : (1.f - ry)) * wz;
                unsigned base = ix + (iy + (unsigned)b1) * res + zoff;
                float2 e0, e1;
                if (even) {
                    float4 v = __ldg((const float4*)(tab + base));
                    e0 = make_float2(v.x, v.y);
                    e1 = make_float2(v.z, v.w);
                } else {
                    e0 = __ldg(tab + base);
                    e1 = __ldg(tab + base + 1u);
                }
                float w0 = wyz * w0x, w1 = wyz * rx;
                ax += w0 * e0.x + w1 * e1.x;
                ay += w0 * e0.y + w1 * e1.y;
            }
        }
    } else {
        // ---- hashed: h = c0 ^ c1*P1 ^ c2*P2, masked. If ix even, the dim0
        // corner pair is (h0, h0^1) -> one aligned float4 covers both.
        unsigned hy0 = iy * PRIME1, hy1 = (iy + 1u) * PRIME1;
        unsigned hz0 = iz * PRIME2, hz1 = (iz + 1u) * PRIME2;
        #pragma unroll
        for (int b2 = 0; b2 < 2; ++b2) {
            float    wz = b2 ? rz : (1.f - rz);
            unsigned hz = b2 ? hz1 : hz0;
            #pragma unroll
            for (int b1 = 0; b1 < 2; ++b1) {
                float    wyz = (b1 ? ry : (1.f - ry)) * wz;
                unsigned tt  = (b1 ? hy1 : hy0) ^ hz;
                unsigned h0  = (ix ^ tt) & HASHMASK;
                float2 e0, e1;
                if (even) {
                    unsigned eb = h0 & ~1u;
                    float4 v = __ldg((const float4*)(tab + eb));
                    if (h0 & 1u) { e0 = make_float2(v.z, v.w); e1 = make_float2(v.x, v.y); }
                    else         { e0 = make_float2(v.x, v.y); e1 = make_float2(v.z, v.w); }
                } else {
                    unsigned h1 = ((ix + 1u) ^ tt) & HASHMASK;
                    e0 = __ldg(tab + h0);
                    e1 = __ldg(tab + h1);
                }
                float w0 = wyz * w0x, w1 = wyz * rx;
                ax += w0 * e0.x + w1 * e1.x;
                ay += w0 * e0.y + w1 * e1.y;
            }
        }
    }

    // Streaming store: keep the 54MB hash table resident in L2.
    __stcs(out + t, make_float2(ax, ay));
}

extern "C" void kernel_launch(void* const* d_in, const int* in_sizes, int n_in,
                              void* d_out, int out_size) {
    // Inputs: x [B,3] f32, embeddings [TOTAL_ROWS,2] f32. Be robust to order.
    const float* x;
    const float2* emb;
    // embeddings has 2*TOTAL_ROWS = 14229504 elements; x has 3*B = 6291456.
    if (in_sizes[0] % 3 == 0 && (n_in < 2 || in_sizes[0] < in_sizes[1])) {
        x   = (const float*)d_in[0];
        emb = (const float2*)d_in[1];
    } else {
        x   = (const float*)d_in[1];
        emb = (const float2*)d_in[0];
    }
    unsigned npoints  = (unsigned)(in_sizes[0] % 3 == 0 && in_sizes[0] < in_sizes[1]
                                   ? in_sizes[0] / 3 : in_sizes[1] / 3);
    unsigned nthreads = npoints * 16u;
    unsigned blocks   = (nthreads + 255u) / 256u;
    hashenc_kernel<<<blocks, 256>>>(x, emb, (float2*)d_out, nthreads);
}